// round 10
// baseline (speedup 1.0000x reference)
#include <cuda_runtime.h>

#define N_NODES 100000
#define IN_DIM 512
#define HIDDEN 16
#define OUT_DIM 64
#define E_CAP 3300000
#define NBLK 391              // ceil(100000/256)

// ---------------- device scratch (no allocations allowed) ----------------
__device__ __align__(16) float g_z[(size_t)N_NODES * HIDDEN];  // (x@W1)*dinv[src]
__device__ __align__(16) float g_h[(size_t)N_NODES * HIDDEN];  // h1*dinv (layer-2 msgs)
__device__ float g_dinv[N_NODES];
__device__ int g_cnt[N_NODES];
__device__ int g_off[N_NODES + 1];
__device__ int g_cur[N_NODES];
__device__ int g_slot[E_CAP];
__device__ int g_bsum[NBLK];
__device__ int g_boff[NBLK];

// ---------------- helpers ----------------
__device__ __forceinline__ unsigned long long fma2(unsigned long long a,
                                                   unsigned long long b,
                                                   unsigned long long c) {
    unsigned long long d;
    asm("fma.rn.f32x2 %0, %1, %2, %3;" : "=l"(d) : "l"(a), "l"(b), "l"(c));
    return d;
}
__device__ __forceinline__ unsigned long long dup2(float v) {
    unsigned long long d;
    asm("mov.b64 %0, {%1, %2};" : "=l"(d) : "f"(v), "f"(v));
    return d;
}

// ---------------- CSR build ----------------

__global__ void k_zero() {
    int i = blockIdx.x * blockDim.x + threadIdx.x;
    if (i < N_NODES) g_cnt[i] = 0;
}

__global__ void k_count(const int* __restrict__ dst, int E4, int E) {
    int t = blockIdx.x * blockDim.x + threadIdx.x;
    if (t < E4) {
        int4 d = __ldg((const int4*)dst + t);
        atomicAdd(&g_cnt[d.x], 1);
        atomicAdd(&g_cnt[d.y], 1);
        atomicAdd(&g_cnt[d.z], 1);
        atomicAdd(&g_cnt[d.w], 1);
    } else if (t == E4) {
        for (int e = E4 * 4; e < E; e++) atomicAdd(&g_cnt[__ldg(dst + e)], 1);
    }
}

// dinv = rsqrt(cnt+1) AND per-block sums of counts (one g_cnt read)
__global__ __launch_bounds__(256) void k_dinv_bsum() {
    __shared__ int sw[8];
    int idx = blockIdx.x * 256 + threadIdx.x;
    int v = (idx < N_NODES) ? g_cnt[idx] : 0;
    if (idx < N_NODES) g_dinv[idx] = rsqrtf((float)(v + 1));  // +1 self loop
    int s = v;
#pragma unroll
    for (int m = 16; m; m >>= 1) s += __shfl_xor_sync(0xffffffffu, s, m);
    if ((threadIdx.x & 31) == 0) sw[threadIdx.x >> 5] = s;
    __syncthreads();
    if (threadIdx.x < 8) {
        int u = sw[threadIdx.x];
#pragma unroll
        for (int m = 4; m; m >>= 1) u += __shfl_xor_sync(0xffu, u, m);
        if (threadIdx.x == 0) g_bsum[blockIdx.x] = u;
    }
}

// single-block exclusive scan of 391 block sums (tiny)
__global__ __launch_bounds__(512) void k_bscan() {
    __shared__ int sc[512];
    int t = threadIdx.x;
    int v = (t < NBLK) ? g_bsum[t] : 0;
    sc[t] = v;
    __syncthreads();
#pragma unroll
    for (int d = 1; d < 512; d <<= 1) {
        int u = (t >= d) ? sc[t - d] : 0;
        __syncthreads();
        sc[t] += u;
        __syncthreads();
    }
    if (t < NBLK) g_boff[t] = sc[t] - v;  // exclusive
}

// block-wide exclusive scan of counts + add block offset -> g_off, g_cur
__global__ __launch_bounds__(256) void k_expand() {
    __shared__ int sw[8];
    int idx = blockIdx.x * 256 + threadIdx.x;
    int lane = threadIdx.x & 31, w = threadIdx.x >> 5;
    int v = (idx < N_NODES) ? g_cnt[idx] : 0;
    int incl = v;
#pragma unroll
    for (int d = 1; d < 32; d <<= 1) {
        int u = __shfl_up_sync(0xffffffffu, incl, d);
        if (lane >= d) incl += u;
    }
    if (lane == 31) sw[w] = incl;
    __syncthreads();
    if (threadIdx.x < 8) {
        int s = sw[threadIdx.x];
        int si = s;
#pragma unroll
        for (int d = 1; d < 8; d <<= 1) {
            int u = __shfl_up_sync(0xffu, si, d);
            if (threadIdx.x >= d) si += u;
        }
        sw[threadIdx.x] = si - s;  // exclusive warp offsets
    }
    __syncthreads();
    int off = g_boff[blockIdx.x] + sw[w] + (incl - v);
    if (idx < N_NODES) {
        g_off[idx] = off;
        g_cur[idx] = off;
        if (idx == N_NODES - 1) g_off[N_NODES] = off + v;
    }
}

// ---------------- FUSED: gemm1 (blocks < G1) + fill (blocks >= G1) ----------
// gemm: 256 threads, 1 row/thread, 256 rows/block, smem-staged x (as R9).
// fill: CSR slot fill via atomic cursor. Independent workloads -> the GPU
// overlaps DRAM-bound gemm with L2-atomic-latency-bound fill.
__global__ __launch_bounds__(256) void k_gemm_fill(const float* __restrict__ x,
                                                   const float* __restrict__ W1,
                                                   const int* __restrict__ src,
                                                   const int* __restrict__ dst,
                                                   int E4, int E, int G1) {
    __shared__ __align__(16) float xs[256 * 36];  // 36 KB
    __shared__ __align__(16) float wst[32 * 16];  // 2 KB

    if (blockIdx.x >= G1) {
        // ---- fill part ----
        int t = (blockIdx.x - G1) * 256 + threadIdx.x;
        if (t < E4) {
            int4 s = __ldg((const int4*)src + t);
            int4 d = __ldg((const int4*)dst + t);
            int p;
            p = atomicAdd(&g_cur[d.x], 1); g_slot[p] = s.x;
            p = atomicAdd(&g_cur[d.y], 1); g_slot[p] = s.y;
            p = atomicAdd(&g_cur[d.z], 1); g_slot[p] = s.z;
            p = atomicAdd(&g_cur[d.w], 1); g_slot[p] = s.w;
        } else if (t == E4) {
            for (int e = E4 * 4; e < E; e++) {
                int p = atomicAdd(&g_cur[__ldg(dst + e)], 1);
                g_slot[p] = __ldg(src + e);
            }
        }
        return;
    }

    // ---- gemm part ----
    int t = threadIdx.x;
    int lrow = t >> 3, lcol = t & 7;
    long long rb = (long long)blockIdx.x * 256;

    unsigned long long acc[8];
#pragma unroll
    for (int i = 0; i < 8; i++) acc[i] = 0ull;

    const ulonglong2* wsp = (const ulonglong2*)wst;
    const float4* w4 = (const float4*)W1;

#pragma unroll 1
    for (int st = 0; st < 16; st++) {
        int k0 = st * 32;
        __syncthreads();  // xs/wst reuse barrier
        if (t < 128) ((float4*)wst)[t] = __ldg(w4 + k0 * 4 + t);
        // stage x tile: 256 rows x 32 floats (32 rows per pass, 8 passes)
#pragma unroll
        for (int i = 0; i < 8; i++) {
            int row = i * 32 + lrow;
            long long gr = rb + row;
            if (gr >= N_NODES) gr = 0;
            float4 v = __ldg((const float4*)(x + gr * IN_DIM + k0) + lcol);
            *(float4*)(xs + row * 36 + lcol * 4) = v;
        }
        __syncthreads();

        const float4* xr = (const float4*)(xs + t * 36);
#pragma unroll
        for (int hc = 0; hc < 2; hc++) {
            float4 v[4];
#pragma unroll
            for (int j = 0; j < 4; j++) v[j] = xr[hc * 4 + j];
#pragma unroll
            for (int j = 0; j < 4; j++) {
#pragma unroll
                for (int jj = 0; jj < 4; jj++) {
                    int kl = hc * 16 + j * 4 + jj;
                    ulonglong2 w0 = wsp[kl * 4 + 0];
                    ulonglong2 w1 = wsp[kl * 4 + 1];
                    ulonglong2 w2 = wsp[kl * 4 + 2];
                    ulonglong2 w3 = wsp[kl * 4 + 3];
                    unsigned long long d0 = dup2(((const float*)&v[j])[jj]);
                    acc[0] = fma2(d0, w0.x, acc[0]);
                    acc[1] = fma2(d0, w0.y, acc[1]);
                    acc[2] = fma2(d0, w1.x, acc[2]);
                    acc[3] = fma2(d0, w1.y, acc[3]);
                    acc[4] = fma2(d0, w2.x, acc[4]);
                    acc[5] = fma2(d0, w2.y, acc[5]);
                    acc[6] = fma2(d0, w3.x, acc[6]);
                    acc[7] = fma2(d0, w3.y, acc[7]);
                }
            }
        }
    }

    long long r0 = rb + t;
    if (r0 < N_NODES) {
        float dv = g_dinv[r0];
        float2* zo = (float2*)(g_z + r0 * HIDDEN);
#pragma unroll
        for (int c = 0; c < 8; c++) {
            float2 p = *(float2*)&acc[c];
            p.x *= dv; p.y *= dv;
            zo[c] = p;
        }
    }
}

// ---------------- layer 1 gather + pointwise (fused) ----------------
// warp = 4 nodes x 2 edge-lanes x 4 quads; edge loop unrolled x2.
__global__ __launch_bounds__(256) void k_gather1(const float* __restrict__ b1) {
    int gw = (blockIdx.x * 256 + threadIdx.x) >> 5;
    int lane = threadIdx.x & 31;
    int ns = lane >> 3, ep = (lane >> 2) & 1, cg = lane & 3;
    int n = gw * 4 + ns;                    // N % 4 == 0 -> always valid
    if (n >= N_NODES) return;

    int e0 = g_off[n], e1 = g_off[n + 1];
    float4 acc = make_float4(0.f, 0.f, 0.f, 0.f);
    float4 acc2 = make_float4(0.f, 0.f, 0.f, 0.f);
    int e = e0 + ep;
    for (; e + 2 < e1; e += 4) {
        int s0 = __ldg(g_slot + e);
        int s1 = __ldg(g_slot + e + 2);
        float4 v0 = __ldg((const float4*)(g_z + (size_t)s0 * HIDDEN) + cg);
        float4 v1 = __ldg((const float4*)(g_z + (size_t)s1 * HIDDEN) + cg);
        acc.x += v0.x; acc.y += v0.y; acc.z += v0.z; acc.w += v0.w;
        acc2.x += v1.x; acc2.y += v1.y; acc2.z += v1.z; acc2.w += v1.w;
    }
    if (e < e1) {
        int s = __ldg(g_slot + e);
        float4 v = __ldg((const float4*)(g_z + (size_t)s * HIDDEN) + cg);
        acc.x += v.x; acc.y += v.y; acc.z += v.z; acc.w += v.w;
    }
    acc.x += acc2.x; acc.y += acc2.y; acc.z += acc2.z; acc.w += acc2.w;
    acc.x += __shfl_xor_sync(0xffffffffu, acc.x, 4);
    acc.y += __shfl_xor_sync(0xffffffffu, acc.y, 4);
    acc.z += __shfl_xor_sync(0xffffffffu, acc.z, 4);
    acc.w += __shfl_xor_sync(0xffffffffu, acc.w, 4);

    if (ep == 0) {
        float di = g_dinv[n];
        float4 bb = __ldg((const float4*)b1 + cg);
        float4 zn = *((const float4*)(g_z + (size_t)n * HIDDEN) + cg);
        float4 r;
        r.x = fmaxf(fmaf(acc.x + zn.x, di, bb.x), 0.f) * di;
        r.y = fmaxf(fmaf(acc.y + zn.y, di, bb.y), 0.f) * di;
        r.z = fmaxf(fmaf(acc.z + zn.z, di, bb.z), 0.f) * di;
        r.w = fmaxf(fmaf(acc.w + zn.w, di, bb.w), 0.f) * di;
        *((float4*)(g_h + (size_t)n * HIDDEN) + cg) = r;
    }
}

// ---------------- layer 2 gather + GEMM2 (fused) ----------------
__global__ __launch_bounds__(256) void k_gather2(const float* __restrict__ W2,
                                                 const float* __restrict__ b2,
                                                 float* __restrict__ out) {
    __shared__ __align__(16) float ws[HIDDEN * OUT_DIM];  // 4 KB
    ((float4*)ws)[threadIdx.x] = ((const float4*)W2)[threadIdx.x];  // 256 float4
    __syncthreads();

    int gw = (blockIdx.x * 256 + threadIdx.x) >> 5;
    int lane = threadIdx.x & 31;
    int ns = lane >> 3, ep = (lane >> 2) & 1, cg = lane & 3;
    int n = gw * 4 + ns;
    if (n >= N_NODES) return;

    int e0 = g_off[n], e1 = g_off[n + 1];
    float4 acc = make_float4(0.f, 0.f, 0.f, 0.f);
    float4 acc2 = make_float4(0.f, 0.f, 0.f, 0.f);
    int e = e0 + ep;
    for (; e + 2 < e1; e += 4) {
        int s0 = __ldg(g_slot + e);
        int s1 = __ldg(g_slot + e + 2);
        float4 v0 = __ldg((const float4*)(g_h + (size_t)s0 * HIDDEN) + cg);
        float4 v1 = __ldg((const float4*)(g_h + (size_t)s1 * HIDDEN) + cg);
        acc.x += v0.x; acc.y += v0.y; acc.z += v0.z; acc.w += v0.w;
        acc2.x += v1.x; acc2.y += v1.y; acc2.z += v1.z; acc2.w += v1.w;
    }
    if (e < e1) {
        int s = __ldg(g_slot + e);
        float4 v = __ldg((const float4*)(g_h + (size_t)s * HIDDEN) + cg);
        acc.x += v.x; acc.y += v.y; acc.z += v.z; acc.w += v.w;
    }
    acc.x += acc2.x; acc.y += acc2.y; acc.z += acc2.z; acc.w += acc2.w;
    acc.x += __shfl_xor_sync(0xffffffffu, acc.x, 4);
    acc.y += __shfl_xor_sync(0xffffffffu, acc.y, 4);
    acc.z += __shfl_xor_sync(0xffffffffu, acc.z, 4);
    acc.w += __shfl_xor_sync(0xffffffffu, acc.w, 4);

    float di = g_dinv[n];
    float4 hn = *((const float4*)(g_h + (size_t)n * HIDDEN) + cg);
    float4 my;
    my.x = (acc.x + hn.x) * di;
    my.y = (acc.y + hn.y) * di;
    my.z = (acc.z + hn.z) * di;
    my.w = (acc.w + hn.w) * di;

    float hk[16];
    int base8 = lane & ~7;
#pragma unroll
    for (int q = 0; q < 4; q++) {
        int sl = base8 + q;
        hk[q * 4 + 0] = __shfl_sync(0xffffffffu, my.x, sl);
        hk[q * 4 + 1] = __shfl_sync(0xffffffffu, my.y, sl);
        hk[q * 4 + 2] = __shfl_sync(0xffffffffu, my.z, sl);
        hk[q * 4 + 3] = __shfl_sync(0xffffffffu, my.w, sl);
    }

    int oc = lane & 7;
    float4 o0 = make_float4(0.f, 0.f, 0.f, 0.f);
    float4 o1 = make_float4(0.f, 0.f, 0.f, 0.f);
#pragma unroll
    for (int k = 0; k < HIDDEN; k++) {
        float xv = hk[k];
        const float4* wr = (const float4*)(ws + k * OUT_DIM + oc * 8);
        float4 wa = wr[0], wb = wr[1];
        o0.x = fmaf(xv, wa.x, o0.x); o0.y = fmaf(xv, wa.y, o0.y);
        o0.z = fmaf(xv, wa.z, o0.z); o0.w = fmaf(xv, wa.w, o0.w);
        o1.x = fmaf(xv, wb.x, o1.x); o1.y = fmaf(xv, wb.y, o1.y);
        o1.z = fmaf(xv, wb.z, o1.z); o1.w = fmaf(xv, wb.w, o1.w);
    }

    const float4* bb = (const float4*)b2 + oc * 2;
    float4 ba = __ldg(bb), bc = __ldg(bb + 1);
    float4* O = (float4*)(out + (size_t)n * OUT_DIM) + oc * 2;
    O[0] = make_float4(o0.x + ba.x, o0.y + ba.y, o0.z + ba.z, o0.w + ba.w);
    O[1] = make_float4(o1.x + bc.x, o1.y + bc.y, o1.z + bc.z, o1.w + bc.w);
}

// ---------------- launch ----------------
extern "C" void kernel_launch(void* const* d_in, const int* in_sizes, int n_in,
                              void* d_out, int out_size) {
    const float* x = nullptr;
    const float* W1 = nullptr;
    const float* b1 = nullptr;
    const float* W2 = nullptr;
    const float* b2 = nullptr;
    const int* ei = nullptr;
    int E = 0;
    for (int i = 0; i < n_in; i++) {
        long long sz = in_sizes[i];
        if (sz == (long long)N_NODES * IN_DIM)      x  = (const float*)d_in[i];
        else if (sz == IN_DIM * HIDDEN)             W1 = (const float*)d_in[i];
        else if (sz == HIDDEN)                      b1 = (const float*)d_in[i];
        else if (sz == HIDDEN * OUT_DIM)            W2 = (const float*)d_in[i];
        else if (sz == OUT_DIM)                     b2 = (const float*)d_in[i];
        else { ei = (const int*)d_in[i]; E = (int)(sz / 2); }
    }
    const int* src = ei;
    const int* dst = ei + E;
    float* out = (float*)d_out;

    const int TB = 256;
    int E4 = E / 4;
    int grid_n  = (N_NODES + TB - 1) / TB;           // 391
    int grid_e4 = (E4 + 1 + TB - 1) / TB;
    int G1 = (N_NODES + 255) / 256;                  // 391 gemm blocks
    int grid_gf = G1 + grid_e4;                      // fused grid
    int grid_gw = (N_NODES / 4 * 32 + TB - 1) / TB;  // 25000 warps -> 3125 blocks

    k_zero<<<grid_n, TB>>>();
    k_count<<<grid_e4, TB>>>(dst, E4, E);
    k_dinv_bsum<<<NBLK, TB>>>();
    k_bscan<<<1, 512>>>();
    k_expand<<<NBLK, TB>>>();
    k_gemm_fill<<<grid_gf, TB>>>(x, W1, src, dst, E4, E, G1);
    k_gather1<<<grid_gw, TB>>>(b1);
    k_gather2<<<grid_gw, TB>>>(W2, b2, out);
}

// round 11
// speedup vs baseline: 1.0218x; 1.0218x over previous
#include <cuda_runtime.h>

#define N_NODES 100000
#define IN_DIM 512
#define HIDDEN 16
#define OUT_DIM 64
#define E_CAP 3300000
#define NBLK 391              // ceil(100000/256)

// ---------------- device scratch (no allocations allowed) ----------------
__device__ __align__(16) float g_z[(size_t)N_NODES * HIDDEN];  // (x@W1)*dinv[src]
__device__ __align__(16) float g_h[(size_t)N_NODES * HIDDEN];  // h1*dinv (layer-2 msgs)
__device__ float g_dinv[N_NODES];
__device__ int g_cnt[N_NODES];        // zero at load; re-zeroed by k_expand each call
__device__ int g_off[N_NODES + 1];
__device__ int g_slot[E_CAP];
__device__ __align__(16) int g_rank[E_CAP];
__device__ int g_bsum[NBLK];
__device__ int g_boff[NBLK];

// ---------------- helpers ----------------
__device__ __forceinline__ unsigned long long fma2(unsigned long long a,
                                                   unsigned long long b,
                                                   unsigned long long c) {
    unsigned long long d;
    asm("fma.rn.f32x2 %0, %1, %2, %3;" : "=l"(d) : "l"(a), "l"(b), "l"(c));
    return d;
}
__device__ __forceinline__ unsigned long long dup2(float v) {
    unsigned long long d;
    asm("mov.b64 %0, {%1, %2};" : "=l"(d) : "f"(v), "f"(v));
    return d;
}

// ---------------- CSR build ----------------

// count in-degree AND record each edge's within-node rank (atomicAdd return)
__global__ void k_count(const int* __restrict__ dst, int E4, int E) {
    int t = blockIdx.x * blockDim.x + threadIdx.x;
    if (t < E4) {
        int4 d = __ldg((const int4*)dst + t);
        int4 r;
        r.x = atomicAdd(&g_cnt[d.x], 1);
        r.y = atomicAdd(&g_cnt[d.y], 1);
        r.z = atomicAdd(&g_cnt[d.z], 1);
        r.w = atomicAdd(&g_cnt[d.w], 1);
        ((int4*)g_rank)[t] = r;
    } else if (t == E4) {
        for (int e = E4 * 4; e < E; e++)
            g_rank[e] = atomicAdd(&g_cnt[__ldg(dst + e)], 1);
    }
}

// dinv = rsqrt(cnt+1) AND per-block sums of counts (one g_cnt read)
__global__ __launch_bounds__(256) void k_dinv_bsum() {
    __shared__ int sw[8];
    int idx = blockIdx.x * 256 + threadIdx.x;
    int v = (idx < N_NODES) ? g_cnt[idx] : 0;
    if (idx < N_NODES) g_dinv[idx] = rsqrtf((float)(v + 1));  // +1 self loop
    int s = v;
#pragma unroll
    for (int m = 16; m; m >>= 1) s += __shfl_xor_sync(0xffffffffu, s, m);
    if ((threadIdx.x & 31) == 0) sw[threadIdx.x >> 5] = s;
    __syncthreads();
    if (threadIdx.x < 8) {
        int u = sw[threadIdx.x];
#pragma unroll
        for (int m = 4; m; m >>= 1) u += __shfl_xor_sync(0xffu, u, m);
        if (threadIdx.x == 0) g_bsum[blockIdx.x] = u;
    }
}

// single-block exclusive scan of 391 block sums (tiny)
__global__ __launch_bounds__(512) void k_bscan() {
    __shared__ int sc[512];
    int t = threadIdx.x;
    int v = (t < NBLK) ? g_bsum[t] : 0;
    sc[t] = v;
    __syncthreads();
#pragma unroll
    for (int d = 1; d < 512; d <<= 1) {
        int u = (t >= d) ? sc[t - d] : 0;
        __syncthreads();
        sc[t] += u;
        __syncthreads();
    }
    if (t < NBLK) g_boff[t] = sc[t] - v;  // exclusive
}

// block-wide exclusive scan of counts + block offset -> g_off; re-zero g_cnt
__global__ __launch_bounds__(256) void k_expand() {
    __shared__ int sw[8];
    int idx = blockIdx.x * 256 + threadIdx.x;
    int lane = threadIdx.x & 31, w = threadIdx.x >> 5;
    int v = (idx < N_NODES) ? g_cnt[idx] : 0;
    int incl = v;
#pragma unroll
    for (int d = 1; d < 32; d <<= 1) {
        int u = __shfl_up_sync(0xffffffffu, incl, d);
        if (lane >= d) incl += u;
    }
    if (lane == 31) sw[w] = incl;
    __syncthreads();
    if (threadIdx.x < 8) {
        int s = sw[threadIdx.x];
        int si = s;
#pragma unroll
        for (int d = 1; d < 8; d <<= 1) {
            int u = __shfl_up_sync(0xffu, si, d);
            if (threadIdx.x >= d) si += u;
        }
        sw[threadIdx.x] = si - s;  // exclusive warp offsets
    }
    __syncthreads();
    int off = g_boff[blockIdx.x] + sw[w] + (incl - v);
    if (idx < N_NODES) {
        g_off[idx] = off;
        g_cnt[idx] = 0;  // ready for next call (graph replay)
        if (idx == N_NODES - 1) g_off[N_NODES] = off + v;
    }
}

// ---------------- FUSED: gemm1 (bids < G1) + atomic-free fill (bids >= G1) --
// launch_bounds(256,3): 3 blocks/SM -> 444 slots; 391 long gemm blocks leave
// ~53 slots that the short fill blocks cycle through DURING the gemm.
__global__ __launch_bounds__(256, 3) void k_gemm_fill(const float* __restrict__ x,
                                                      const float* __restrict__ W1,
                                                      const int* __restrict__ src,
                                                      const int* __restrict__ dst,
                                                      int E8, int E, int G1) {
    __shared__ __align__(16) float xs[256 * 36];  // 36 KB
    __shared__ __align__(16) float wst[32 * 16];  // 2 KB

    if (blockIdx.x >= G1) {
        // ---- fill part: slot[off[dst]+rank] = src, 8 edges/thread ----
        int ft = (blockIdx.x - G1) * 256 + threadIdx.x;
        if (ft < E8) {
            const int4* s4 = (const int4*)src;
            const int4* d4 = (const int4*)dst;
            const int4* r4 = (const int4*)g_rank;
#pragma unroll
            for (int h = 0; h < 2; h++) {
                int4 s = __ldg(s4 + 2 * ft + h);
                int4 d = __ldg(d4 + 2 * ft + h);
                int4 r = __ldg(r4 + 2 * ft + h);
                g_slot[__ldg(&g_off[d.x]) + r.x] = s.x;
                g_slot[__ldg(&g_off[d.y]) + r.y] = s.y;
                g_slot[__ldg(&g_off[d.z]) + r.z] = s.z;
                g_slot[__ldg(&g_off[d.w]) + r.w] = s.w;
            }
        } else if (ft == E8) {
            for (int e = E8 * 8; e < E; e++)
                g_slot[__ldg(&g_off[__ldg(dst + e)]) + g_rank[e]] = __ldg(src + e);
        }
        return;
    }

    // ---- gemm part (R10 body) ----
    int t = threadIdx.x;
    int lrow = t >> 3, lcol = t & 7;
    long long rb = (long long)blockIdx.x * 256;

    unsigned long long acc[8];
#pragma unroll
    for (int i = 0; i < 8; i++) acc[i] = 0ull;

    const ulonglong2* wsp = (const ulonglong2*)wst;
    const float4* w4 = (const float4*)W1;

#pragma unroll 1
    for (int st = 0; st < 16; st++) {
        int k0 = st * 32;
        __syncthreads();  // xs/wst reuse barrier
        if (t < 128) ((float4*)wst)[t] = __ldg(w4 + k0 * 4 + t);
#pragma unroll
        for (int i = 0; i < 8; i++) {
            int row = i * 32 + lrow;
            long long gr = rb + row;
            if (gr >= N_NODES) gr = 0;
            float4 v = __ldg((const float4*)(x + gr * IN_DIM + k0) + lcol);
            *(float4*)(xs + row * 36 + lcol * 4) = v;
        }
        __syncthreads();

        const float4* xr = (const float4*)(xs + t * 36);
#pragma unroll
        for (int hc = 0; hc < 2; hc++) {
            float4 v[4];
#pragma unroll
            for (int j = 0; j < 4; j++) v[j] = xr[hc * 4 + j];
#pragma unroll
            for (int j = 0; j < 4; j++) {
#pragma unroll
                for (int jj = 0; jj < 4; jj++) {
                    int kl = hc * 16 + j * 4 + jj;
                    ulonglong2 w0 = wsp[kl * 4 + 0];
                    ulonglong2 w1 = wsp[kl * 4 + 1];
                    ulonglong2 w2 = wsp[kl * 4 + 2];
                    ulonglong2 w3 = wsp[kl * 4 + 3];
                    unsigned long long d0 = dup2(((const float*)&v[j])[jj]);
                    acc[0] = fma2(d0, w0.x, acc[0]);
                    acc[1] = fma2(d0, w0.y, acc[1]);
                    acc[2] = fma2(d0, w1.x, acc[2]);
                    acc[3] = fma2(d0, w1.y, acc[3]);
                    acc[4] = fma2(d0, w2.x, acc[4]);
                    acc[5] = fma2(d0, w2.y, acc[5]);
                    acc[6] = fma2(d0, w3.x, acc[6]);
                    acc[7] = fma2(d0, w3.y, acc[7]);
                }
            }
        }
    }

    long long r0 = rb + t;
    if (r0 < N_NODES) {
        float dv = g_dinv[r0];
        float2* zo = (float2*)(g_z + r0 * HIDDEN);
#pragma unroll
        for (int c = 0; c < 8; c++) {
            float2 p = *(float2*)&acc[c];
            p.x *= dv; p.y *= dv;
            zo[c] = p;
        }
    }
}

// ---------------- layer 1 gather + pointwise (fused) ----------------
// warp = 4 nodes x 2 edge-lanes x 4 quads; edge loop unrolled x2.
__global__ __launch_bounds__(256) void k_gather1(const float* __restrict__ b1) {
    int gw = (blockIdx.x * 256 + threadIdx.x) >> 5;
    int lane = threadIdx.x & 31;
    int ns = lane >> 3, ep = (lane >> 2) & 1, cg = lane & 3;
    int n = gw * 4 + ns;                    // N % 4 == 0 -> always valid
    if (n >= N_NODES) return;

    int e0 = g_off[n], e1 = g_off[n + 1];
    float4 acc = make_float4(0.f, 0.f, 0.f, 0.f);
    float4 acc2 = make_float4(0.f, 0.f, 0.f, 0.f);
    int e = e0 + ep;
    for (; e + 2 < e1; e += 4) {
        int s0 = __ldg(g_slot + e);
        int s1 = __ldg(g_slot + e + 2);
        float4 v0 = __ldg((const float4*)(g_z + (size_t)s0 * HIDDEN) + cg);
        float4 v1 = __ldg((const float4*)(g_z + (size_t)s1 * HIDDEN) + cg);
        acc.x += v0.x; acc.y += v0.y; acc.z += v0.z; acc.w += v0.w;
        acc2.x += v1.x; acc2.y += v1.y; acc2.z += v1.z; acc2.w += v1.w;
    }
    if (e < e1) {
        int s = __ldg(g_slot + e);
        float4 v = __ldg((const float4*)(g_z + (size_t)s * HIDDEN) + cg);
        acc.x += v.x; acc.y += v.y; acc.z += v.z; acc.w += v.w;
    }
    acc.x += acc2.x; acc.y += acc2.y; acc.z += acc2.z; acc.w += acc2.w;
    acc.x += __shfl_xor_sync(0xffffffffu, acc.x, 4);
    acc.y += __shfl_xor_sync(0xffffffffu, acc.y, 4);
    acc.z += __shfl_xor_sync(0xffffffffu, acc.z, 4);
    acc.w += __shfl_xor_sync(0xffffffffu, acc.w, 4);

    if (ep == 0) {
        float di = g_dinv[n];
        float4 bb = __ldg((const float4*)b1 + cg);
        float4 zn = *((const float4*)(g_z + (size_t)n * HIDDEN) + cg);
        float4 r;
        r.x = fmaxf(fmaf(acc.x + zn.x, di, bb.x), 0.f) * di;
        r.y = fmaxf(fmaf(acc.y + zn.y, di, bb.y), 0.f) * di;
        r.z = fmaxf(fmaf(acc.z + zn.z, di, bb.z), 0.f) * di;
        r.w = fmaxf(fmaf(acc.w + zn.w, di, bb.w), 0.f) * di;
        *((float4*)(g_h + (size_t)n * HIDDEN) + cg) = r;
    }
}

// ---------------- layer 2 gather + GEMM2 (fused) ----------------
__global__ __launch_bounds__(256) void k_gather2(const float* __restrict__ W2,
                                                 const float* __restrict__ b2,
                                                 float* __restrict__ out) {
    __shared__ __align__(16) float ws[HIDDEN * OUT_DIM];  // 4 KB
    ((float4*)ws)[threadIdx.x] = ((const float4*)W2)[threadIdx.x];  // 256 float4
    __syncthreads();

    int gw = (blockIdx.x * 256 + threadIdx.x) >> 5;
    int lane = threadIdx.x & 31;
    int ns = lane >> 3, ep = (lane >> 2) & 1, cg = lane & 3;
    int n = gw * 4 + ns;
    if (n >= N_NODES) return;

    int e0 = g_off[n], e1 = g_off[n + 1];
    float4 acc = make_float4(0.f, 0.f, 0.f, 0.f);
    float4 acc2 = make_float4(0.f, 0.f, 0.f, 0.f);
    int e = e0 + ep;
    for (; e + 2 < e1; e += 4) {
        int s0 = __ldg(g_slot + e);
        int s1 = __ldg(g_slot + e + 2);
        float4 v0 = __ldg((const float4*)(g_h + (size_t)s0 * HIDDEN) + cg);
        float4 v1 = __ldg((const float4*)(g_h + (size_t)s1 * HIDDEN) + cg);
        acc.x += v0.x; acc.y += v0.y; acc.z += v0.z; acc.w += v0.w;
        acc2.x += v1.x; acc2.y += v1.y; acc2.z += v1.z; acc2.w += v1.w;
    }
    if (e < e1) {
        int s = __ldg(g_slot + e);
        float4 v = __ldg((const float4*)(g_h + (size_t)s * HIDDEN) + cg);
        acc.x += v.x; acc.y += v.y; acc.z += v.z; acc.w += v.w;
    }
    acc.x += acc2.x; acc.y += acc2.y; acc.z += acc2.z; acc.w += acc2.w;
    acc.x += __shfl_xor_sync(0xffffffffu, acc.x, 4);
    acc.y += __shfl_xor_sync(0xffffffffu, acc.y, 4);
    acc.z += __shfl_xor_sync(0xffffffffu, acc.z, 4);
    acc.w += __shfl_xor_sync(0xffffffffu, acc.w, 4);

    float di = g_dinv[n];
    float4 hn = *((const float4*)(g_h + (size_t)n * HIDDEN) + cg);
    float4 my;
    my.x = (acc.x + hn.x) * di;
    my.y = (acc.y + hn.y) * di;
    my.z = (acc.z + hn.z) * di;
    my.w = (acc.w + hn.w) * di;

    float hk[16];
    int base8 = lane & ~7;
#pragma unroll
    for (int q = 0; q < 4; q++) {
        int sl = base8 + q;
        hk[q * 4 + 0] = __shfl_sync(0xffffffffu, my.x, sl);
        hk[q * 4 + 1] = __shfl_sync(0xffffffffu, my.y, sl);
        hk[q * 4 + 2] = __shfl_sync(0xffffffffu, my.z, sl);
        hk[q * 4 + 3] = __shfl_sync(0xffffffffu, my.w, sl);
    }

    int oc = lane & 7;
    float4 o0 = make_float4(0.f, 0.f, 0.f, 0.f);
    float4 o1 = make_float4(0.f, 0.f, 0.f, 0.f);
#pragma unroll
    for (int k = 0; k < HIDDEN; k++) {
        float xv = hk[k];
        const float4* wr = (const float4*)(ws + k * OUT_DIM + oc * 8);
        float4 wa = wr[0], wb = wr[1];
        o0.x = fmaf(xv, wa.x, o0.x); o0.y = fmaf(xv, wa.y, o0.y);
        o0.z = fmaf(xv, wa.z, o0.z); o0.w = fmaf(xv, wa.w, o0.w);
        o1.x = fmaf(xv, wb.x, o1.x); o1.y = fmaf(xv, wb.y, o1.y);
        o1.z = fmaf(xv, wb.z, o1.z); o1.w = fmaf(xv, wb.w, o1.w);
    }

    const float4* bb = (const float4*)b2 + oc * 2;
    float4 ba = __ldg(bb), bc = __ldg(bb + 1);
    float4* O = (float4*)(out + (size_t)n * OUT_DIM) + oc * 2;
    O[0] = make_float4(o0.x + ba.x, o0.y + ba.y, o0.z + ba.z, o0.w + ba.w);
    O[1] = make_float4(o1.x + bc.x, o1.y + bc.y, o1.z + bc.z, o1.w + bc.w);
}

// ---------------- launch ----------------
extern "C" void kernel_launch(void* const* d_in, const int* in_sizes, int n_in,
                              void* d_out, int out_size) {
    const float* x = nullptr;
    const float* W1 = nullptr;
    const float* b1 = nullptr;
    const float* W2 = nullptr;
    const float* b2 = nullptr;
    const int* ei = nullptr;
    int E = 0;
    for (int i = 0; i < n_in; i++) {
        long long sz = in_sizes[i];
        if (sz == (long long)N_NODES * IN_DIM)      x  = (const float*)d_in[i];
        else if (sz == IN_DIM * HIDDEN)             W1 = (const float*)d_in[i];
        else if (sz == HIDDEN)                      b1 = (const float*)d_in[i];
        else if (sz == HIDDEN * OUT_DIM)            W2 = (const float*)d_in[i];
        else if (sz == OUT_DIM)                     b2 = (const float*)d_in[i];
        else { ei = (const int*)d_in[i]; E = (int)(sz / 2); }
    }
    const int* src = ei;
    const int* dst = ei + E;
    float* out = (float*)d_out;

    const int TB = 256;
    int E4 = E / 4;
    int E8 = E / 8;
    int grid_e4 = (E4 + 1 + TB - 1) / TB;
    int grid_f8 = (E8 + 1 + TB - 1) / TB;           // fill blocks (8 edges/thr)
    int G1 = (N_NODES + 255) / 256;                  // 391 gemm blocks
    int grid_gw = (N_NODES / 4 * 32 + TB - 1) / TB;  // 25000 warps -> 3125 blocks

    k_count<<<grid_e4, TB>>>(dst, E4, E);
    k_dinv_bsum<<<NBLK, TB>>>();
    k_bscan<<<1, 512>>>();
    k_expand<<<NBLK, TB>>>();
    k_gemm_fill<<<G1 + grid_f8, TB>>>(x, W1, src, dst, E8, E, G1);
    k_gather1<<<grid_gw, TB>>>(b1);
    k_gather2<<<grid_gw, TB>>>(W2, b2, out);
}